// round 3
// baseline (speedup 1.0000x reference)
#include <cuda_runtime.h>
#include <cstdint>

// Problem constants (fixed by the reference):
//   x: (B=16384, F=128) f32, p: (B, C=8) f32,
//   W: (F, C*C=64, R=64) f32 -> flat (128, 4096),
//   b: (C, C, R) f32 -> flat (4096), out: (B, C, R) f32 -> (B, 512)
// logits[b, n] = sum_f x[b,f] * W[f*4096 + n],  n = c*512 + d*64 + r
// M = softmax over d;  out[b, d*64+r] = sum_c p[b,c] * M[b, c, d, r]

#define NTHREADS 256
#define BM 32          // batch rows per block
#define TM 8           // rows per thread (ty in 0..3)
#define KKC 16         // K-chunk depth
#define NCHUNK 8       // 128 / 16
#define NC 8           // C
#define NR 64          // R
#define BN 512         // C * R (one c-group of columns)
#define NF 128         // features
#define AS_STRIDE 36   // padded stride for transposed x tile (16B-aligned reads)

__device__ __forceinline__ uint32_t smem_u32(const void* p) {
    return (uint32_t)__cvta_generic_to_shared(p);
}

__device__ __forceinline__ void prefetch_chunk(const float* __restrict__ W,
                                               float* __restrict__ Bs,
                                               int c, int kk, int buf, int tid) {
    const float* src_base = W + (size_t)kk * KKC * 4096 + c * BN;
    float* dst_base = Bs + buf * (KKC * BN);
    // 16*512 floats = 2048 float4; 8 per thread
    #pragma unroll
    for (int j = 0; j < 8; j++) {
        int idx = tid + j * NTHREADS;   // float4 index
        int k   = idx >> 7;             // 128 float4 per 512-wide row
        int n4  = idx & 127;
        uint32_t dsh = smem_u32(dst_base + k * BN + n4 * 4);
        const float* src = src_base + (size_t)k * 4096 + n4 * 4;
        asm volatile("cp.async.cg.shared.global [%0], [%1], 16;\n"
                     :: "r"(dsh), "l"(src));
    }
    asm volatile("cp.async.commit_group;\n");
}

__global__ __launch_bounds__(NTHREADS, 1)
void crowds_fused_kernel(const float* __restrict__ x,
                         const float* __restrict__ p,
                         const float* __restrict__ W,
                         const float* __restrict__ bias,
                         float* __restrict__ out) {
    extern __shared__ float smem[];
    float* As    = smem;                       // [128][AS_STRIDE] transposed x tile
    float* Bs    = As + NF * AS_STRIDE;        // [2][16][512] W chunks
    float* biass = Bs + 2 * KKC * BN;          // [4096]
    float* ps    = biass + NC * BN;            // [32][8]

    const int tid = threadIdx.x;
    const int tx  = tid & 63;                  // r index (0..63)
    const int ty  = tid >> 6;                  // row group (0..3)
    const int rowbase = blockIdx.x * BM;

    // ---- stage x tile (transposed), bias, p ----
    for (int i = tid; i < BM * (NF / 4); i += NTHREADS) {
        int row = i >> 5;                      // 32 float4 per row
        int c4  = i & 31;
        float4 v = *reinterpret_cast<const float4*>(
            x + (size_t)(rowbase + row) * NF + c4 * 4);
        As[(c4 * 4 + 0) * AS_STRIDE + row] = v.x;
        As[(c4 * 4 + 1) * AS_STRIDE + row] = v.y;
        As[(c4 * 4 + 2) * AS_STRIDE + row] = v.z;
        As[(c4 * 4 + 3) * AS_STRIDE + row] = v.w;
    }
    for (int i = tid; i < NC * BN; i += NTHREADS) biass[i] = bias[i];
    if (tid < BM * NC) ps[tid] = p[(size_t)rowbase * NC + tid];
    __syncthreads();

    float outreg[TM][NC];
    #pragma unroll
    for (int m = 0; m < TM; m++)
        #pragma unroll
        for (int d = 0; d < NC; d++) outreg[m][d] = 0.f;

    for (int c = 0; c < NC; c++) {
        float acc[TM][NC];
        #pragma unroll
        for (int m = 0; m < TM; m++)
            #pragma unroll
            for (int d = 0; d < NC; d++) acc[m][d] = 0.f;

        prefetch_chunk(W, Bs, c, 0, 0, tid);

        for (int kk = 0; kk < NCHUNK; kk++) {
            if (kk + 1 < NCHUNK) {
                prefetch_chunk(W, Bs, c, kk + 1, (kk + 1) & 1, tid);
                asm volatile("cp.async.wait_group 1;\n");
            } else {
                asm volatile("cp.async.wait_group 0;\n");
            }
            __syncthreads();

            const float* B0 = Bs + (kk & 1) * (KKC * BN);
            #pragma unroll
            for (int k = 0; k < KKC; k++) {
                // FIX (R1 bug): use the GLOBAL feature index kk*KKC + k into As,
                // not the chunk-local k. Previous round contracted x[:,0:16]
                // against every W chunk -> rel_err 0.112.
                const float* Arow = &As[(kk * KKC + k) * AS_STRIDE + ty * TM];
                float4 a0 = *reinterpret_cast<const float4*>(Arow);
                float4 a1 = *reinterpret_cast<const float4*>(Arow + 4);
                float a[TM] = {a0.x, a0.y, a0.z, a0.w, a1.x, a1.y, a1.z, a1.w};
                float bf[NC];
                #pragma unroll
                for (int d = 0; d < NC; d++) bf[d] = B0[k * BN + d * NR + tx];
                #pragma unroll
                for (int m = 0; m < TM; m++)
                    #pragma unroll
                    for (int d = 0; d < NC; d++)
                        acc[m][d] = fmaf(a[m], bf[d], acc[m][d]);
            }
            __syncthreads();
        }

        // ---- epilogue for this c: bias + row softmax over d + p-weighting ----
        #pragma unroll
        for (int m = 0; m < TM; m++) {
            float v[NC];
            float mx = -1e30f;
            #pragma unroll
            for (int d = 0; d < NC; d++) {
                v[d] = acc[m][d] + biass[c * BN + d * NR + tx];
                mx = fmaxf(mx, v[d]);
            }
            float s = 0.f;
            #pragma unroll
            for (int d = 0; d < NC; d++) {
                v[d] = __expf(v[d] - mx);
                s += v[d];
            }
            float pv = ps[(ty * TM + m) * NC + c];
            float sc = __fdividef(pv, s);
            #pragma unroll
            for (int d = 0; d < NC; d++) outreg[m][d] += v[d] * sc;
        }
    }

    // ---- write output (B, C, R): fully covers d_out ----
    #pragma unroll
    for (int m = 0; m < TM; m++) {
        size_t row = rowbase + ty * TM + m;
        #pragma unroll
        for (int d = 0; d < NC; d++)
            out[row * BN + d * NR + tx] = outreg[m][d];
    }
}

extern "C" void kernel_launch(void* const* d_in, const int* in_sizes, int n_in,
                              void* d_out, int out_size) {
    const float* x    = (const float*)d_in[0];   // (B, 128)
    const float* p    = (const float*)d_in[1];   // (B, 8)
    const float* W    = (const float*)d_in[2];   // (128, 4096)
    const float* bias = (const float*)d_in[3];   // (4096,)
    float* out = (float*)d_out;

    int B = in_sizes[0] / NF;                    // 16384
    int grid = B / BM;                           // 512

    size_t smem_bytes = (NF * AS_STRIDE + 2 * KKC * BN + NC * BN + BM * NC) * sizeof(float);
    cudaFuncSetAttribute(crowds_fused_kernel,
                         cudaFuncAttributeMaxDynamicSharedMemorySize,
                         (int)smem_bytes);

    crowds_fused_kernel<<<grid, NTHREADS, smem_bytes>>>(x, p, W, bias, out);
}

// round 5
// speedup vs baseline: 1.0079x; 1.0079x over previous
#include <cuda_runtime.h>
#include <cstdint>

// ============================================================
// x(16384,128) f32, p(16384,8) f32, W(128,4096) f32, b(4096) f32
// logits[b,n] = sum_f x[b,f]*W[f,n],  n = c*512 + d*64 + r
// out[b, d*64+r] = sum_c p[b,c] * softmax_d(logits[b,c,:,r])
//
// SIMT fp32, but issue-optimized:
//  - fma.rn.f32x2 packed over the d axis (32 FFMA2 / k-step)
//  - W permuted (prep kernel) so d is contiguous -> 2x LDS.128 B-side
//  - x staged duplicated {v,v}  -> 4x broadcast LDS.128 A-side, no packs
// ============================================================

#define NTHREADS 256
#define BM 32          // batch rows per block
#define TM 8           // rows per thread (ty in 0..3)
#define KKC 16         // K-chunk depth
#define NCHUNK 8       // 128 / 16
#define NC 8
#define NR 64
#define BN 512         // C*R columns per c-group
#define NF 128

typedef unsigned long long u64t;

// permuted W scratch: Wp[((c*8+kk)*16+k)*512 + half*256 + r*4 + dd]
// where global k = kk*16+k, d = half*4+dd
__device__ __align__(16) float g_Wp[128 * 4096];

__device__ __forceinline__ uint32_t smem_u32(const void* p) {
    return (uint32_t)__cvta_generic_to_shared(p);
}
__device__ __forceinline__ void ffma2(u64t& d, u64t a, u64t b) {
    asm("fma.rn.f32x2 %0, %1, %2, %0;" : "+l"(d) : "l"(a), "l"(b));
}

// -------- prep: permute W --------
__global__ void prep_w_kernel(const float* __restrict__ W) {
    int idx = blockIdx.x * 256 + threadIdx.x;   // 128*4096
    int k = idx >> 12;
    int n = idx & 4095;
    int c = n >> 9, d = (n >> 6) & 7, r = n & 63;
    int kk = k >> 4, ki = k & 15;
    int dst = ((c * NCHUNK + kk) * KKC + ki) * 512 + (d >> 2) * 256 + r * 4 + (d & 3);
    g_Wp[dst] = W[(size_t)k * 4096 + n];
}

// -------- smem layout (floats) --------
#define SM_AS2   0                       // [128 k][32 rows] float2 dup = 8192 f
#define SM_BS    8192                    // 2 x [16][512] = 16384 f
#define SM_BIAS  (SM_BS + 2 * KKC * 512) // 4096 f
#define SM_P     (SM_BIAS + NC * BN)     // 256 f
#define SM_NFLT  (SM_P + 256)

__device__ __forceinline__ void prefetch_chunk(float* __restrict__ BsBase,
                                               int c, int kk, int buf, int tid) {
    const float* src = g_Wp + (size_t)(c * NCHUNK + kk) * (KKC * 512);
    uint32_t dst = smem_u32(BsBase + buf * (KKC * 512));
    #pragma unroll
    for (int j = 0; j < 8; j++) {
        int idx = tid + j * NTHREADS;    // float4 index, 2048 total
        asm volatile("cp.async.cg.shared.global [%0], [%1], 16;"
                     :: "r"(dst + idx * 16), "l"(src + idx * 4));
    }
    asm volatile("cp.async.commit_group;");
}

__global__ __launch_bounds__(NTHREADS, 1)
void crowds_fused_kernel(const float* __restrict__ x,
                         const float* __restrict__ p,
                         const float* __restrict__ bias,
                         float* __restrict__ out) {
    extern __shared__ float smem[];
    float* As2   = smem + SM_AS2;
    float* Bs    = smem + SM_BS;
    float* biass = smem + SM_BIAS;
    float* ps    = smem + SM_P;

    const int tid = threadIdx.x;
    const int tx  = tid & 63;            // r index 0..63
    const int ty  = tid >> 6;            // row group 0..3
    const int rowbase = blockIdx.x * BM;

    // ---- stage x duplicated {v,v}: As2[(k*32+row)*2 + {0,1}] ----
    for (int i = tid; i < BM * (NF / 4); i += NTHREADS) {
        int row = i >> 5;
        int c4  = i & 31;
        float4 v = *reinterpret_cast<const float4*>(
            x + (size_t)(rowbase + row) * NF + c4 * 4);
        float2* dst0 = reinterpret_cast<float2*>(As2) + ((c4 * 4 + 0) * BM + row);
        float2* dst1 = reinterpret_cast<float2*>(As2) + ((c4 * 4 + 1) * BM + row);
        float2* dst2 = reinterpret_cast<float2*>(As2) + ((c4 * 4 + 2) * BM + row);
        float2* dst3 = reinterpret_cast<float2*>(As2) + ((c4 * 4 + 3) * BM + row);
        *dst0 = make_float2(v.x, v.x);
        *dst1 = make_float2(v.y, v.y);
        *dst2 = make_float2(v.z, v.z);
        *dst3 = make_float2(v.w, v.w);
    }
    for (int i = tid; i < (NC * BN) / 4; i += NTHREADS)
        reinterpret_cast<float4*>(biass)[i] =
            reinterpret_cast<const float4*>(bias)[i];
    if (tid < 64)
        reinterpret_cast<float4*>(ps)[tid] =
            reinterpret_cast<const float4*>(p + (size_t)rowbase * NC)[tid];
    __syncthreads();

    float outreg[TM][NC];
    #pragma unroll
    for (int m = 0; m < TM; m++)
        #pragma unroll
        for (int d = 0; d < NC; d++) outreg[m][d] = 0.f;

    for (int c = 0; c < NC; c++) {
        u64t acc[TM][4];                 // packed pairs over d: [m][d/2-pair]
        #pragma unroll
        for (int m = 0; m < TM; m++)
            #pragma unroll
            for (int j = 0; j < 4; j++) acc[m][j] = 0ull;

        prefetch_chunk(Bs, c, 0, 0, tid);

        for (int kk = 0; kk < NCHUNK; kk++) {
            if (kk + 1 < NCHUNK) {
                prefetch_chunk(Bs, c, kk + 1, (kk + 1) & 1, tid);
                asm volatile("cp.async.wait_group 1;");
            } else {
                asm volatile("cp.async.wait_group 0;");
            }
            __syncthreads();

            const float* B0 = Bs + (kk & 1) * (KKC * 512);
            #pragma unroll
            for (int ki = 0; ki < KKC; ki++) {
                const int gk = kk * KKC + ki;        // GLOBAL feature index
                // a: 8 duplicated pairs, broadcast LDS.128 x4
                const u64t* ap = reinterpret_cast<const u64t*>(As2) + (gk * BM + ty * TM);
                u64t a2[TM];
                #pragma unroll
                for (int q = 0; q < 4; q++) {
                    ulonglong2 av = *reinterpret_cast<const ulonglong2*>(ap + q * 2);
                    a2[q * 2 + 0] = av.x;
                    a2[q * 2 + 1] = av.y;
                }
                // b: 8 d-values contiguous as two float4 groups
                const float* bp = B0 + ki * 512 + tx * 4;
                ulonglong2 b01 = *reinterpret_cast<const ulonglong2*>(bp);
                ulonglong2 b23 = *reinterpret_cast<const ulonglong2*>(bp + 256);
                u64t b2[4] = {b01.x, b01.y, b23.x, b23.y};
                #pragma unroll
                for (int m = 0; m < TM; m++)
                    #pragma unroll
                    for (int j = 0; j < 4; j++)
                        ffma2(acc[m][j], a2[m], b2[j]);
            }
            __syncthreads();
        }

        // ---- epilogue: bias + softmax over d + p-weighting ----
        #pragma unroll
        for (int m = 0; m < TM; m++) {
            float v[NC];
            #pragma unroll
            for (int j = 0; j < 4; j++) {
                uint2 u = *reinterpret_cast<uint2*>(&acc[m][j]);
                v[2 * j + 0] = __uint_as_float(u.x);
                v[2 * j + 1] = __uint_as_float(u.y);
            }
            float mx = -1e30f;
            #pragma unroll
            for (int d = 0; d < NC; d++) {
                v[d] += biass[c * BN + d * NR + tx];
                mx = fmaxf(mx, v[d]);
            }
            float s = 0.f;
            #pragma unroll
            for (int d = 0; d < NC; d++) {
                v[d] = __expf(v[d] - mx);
                s += v[d];
            }
            float pv = ps[(ty * TM + m) * NC + c];
            float sc = __fdividef(pv, s);
            #pragma unroll
            for (int d = 0; d < NC; d++) outreg[m][d] += v[d] * sc;
        }
    }

    // ---- write output (B, C, R) ----
    #pragma unroll
    for (int m = 0; m < TM; m++) {
        size_t row = rowbase + ty * TM + m;
        #pragma unroll
        for (int d = 0; d < NC; d++)
            out[row * BN + d * NR + tx] = outreg[m][d];
    }
}

extern "C" void kernel_launch(void* const* d_in, const int* in_sizes, int n_in,
                              void* d_out, int out_size) {
    const float* x    = (const float*)d_in[0];   // (16384, 128)
    const float* p    = (const float*)d_in[1];   // (16384, 8)
    const float* W    = (const float*)d_in[2];   // (128, 4096)
    const float* bias = (const float*)d_in[3];   // (4096,)
    float* out = (float*)d_out;

    int B = in_sizes[0] / NF;                    // 16384
    int grid = B / BM;                           // 512

    prep_w_kernel<<<(128 * 4096) / 256, 256>>>(W);

    size_t smem_bytes = SM_NFLT * sizeof(float); // ~116 KB
    cudaFuncSetAttribute(crowds_fused_kernel,
                         cudaFuncAttributeMaxDynamicSharedMemorySize,
                         (int)smem_bytes);
    crowds_fused_kernel<<<grid, NTHREADS, smem_bytes>>>(x, p, bias, out);
}

// round 6
// speedup vs baseline: 2.4020x; 2.3832x over previous
#include <cuda_runtime.h>
#include <cuda_bf16.h>
#include <cstdint>

// ============================================================
// x(16384,128) f32, p(16384,8) f32, W(128,4096) f32, b(4096) f32
// logits[b,n] = sum_f x[b,f]*W[f,n],  n = c*512 + d*64 + r
// out[b, d*64+r] = sum_c p[b,c] * softmax_d(logits[b,c,:,r])
//
// bf16x3-split warp-level mma.sync (HMMA) GEMM, columns permuted
// n' = r*64 + c*8 + d so each n8 mma tile is one softmax d-group
// (softmax = 2 quad shuffles). Prep kernels bake bf16 hi/lo images
// with 16B-chunk XOR swizzle for conflict-free ldmatrix.
// ============================================================

#define NF 128

// -------- device scratch --------
__device__ __align__(1024) uint8_t g_Whi[32u * 32768];   // [slab*2+kh][256n][8ch][16B]
__device__ __align__(1024) uint8_t g_Wlo[32u * 32768];
__device__ __align__(1024) uint8_t g_Xhi[128u * 32768];  // [rowblk][128r][16ch][16B]
__device__ __align__(1024) uint8_t g_Xlo[128u * 32768];
__device__ __align__(16) float g_biasp[4096];

// -------- smem byte offsets --------
#define SM_XHI   0
#define SM_XLO   32768
#define SM_W     65536            // 2 slots x 65536 (hi 32K + lo 32K each)
#define SM_STAGE 131072           // = slot 1 (reused after its HMMAs drain)
#define SM_BIAS  196608
#define SM_P     212992
#define SM_TOT   217088

__device__ __forceinline__ uint32_t smem_u32(const void* p) {
    return (uint32_t)__cvta_generic_to_shared(p);
}
__device__ __forceinline__ void cp16(uint32_t dst, const void* src) {
    asm volatile("cp.async.cg.shared.global [%0], [%1], 16;" :: "r"(dst), "l"(src));
}
#define LDSM4(r, a) \
    asm volatile("ldmatrix.sync.aligned.m8n8.x4.shared.b16 {%0,%1,%2,%3}, [%4];" \
        : "=r"((r)[0]), "=r"((r)[1]), "=r"((r)[2]), "=r"((r)[3]) : "r"(a))

__device__ __forceinline__ void mma16816(float* c, const uint32_t* a,
                                         uint32_t b0, uint32_t b1) {
    asm volatile(
        "mma.sync.aligned.m16n8k16.row.col.f32.bf16.bf16.f32 "
        "{%0,%1,%2,%3}, {%4,%5,%6,%7}, {%8,%9}, {%0,%1,%2,%3};"
        : "+f"(c[0]), "+f"(c[1]), "+f"(c[2]), "+f"(c[3])
        : "r"(a[0]), "r"(a[1]), "r"(a[2]), "r"(a[3]), "r"(b0), "r"(b1));
}
__device__ __forceinline__ uint32_t pack2bf(float a, float b) {
    __nv_bfloat162 h;
    h.x = __float2bfloat16(a);
    h.y = __float2bfloat16(b);
    return *reinterpret_cast<uint32_t*>(&h);
}

// ============================================================
// Prep: W -> permuted, split, swizzled images; bias -> permuted
// ============================================================
__global__ void prep_w_kernel(const float* __restrict__ W,
                              const float* __restrict__ bias) {
    int idx = blockIdx.x * 256 + threadIdx.x;   // 64*4096
    if (idx < 4096) {
        int n = idx;
        int c = n >> 9, d = (n >> 6) & 7, r = n & 63;
        g_biasp[r * 64 + c * 8 + d] = bias[n];
    }
    int f2 = (idx >> 12) * 2;                   // even feature
    int n  = idx & 4095;
    float w0 = W[(size_t)f2 * 4096 + n];
    float w1 = W[(size_t)(f2 + 1) * 4096 + n];
    float h0 = __bfloat162float(__float2bfloat16(w0));
    float h1 = __bfloat162float(__float2bfloat16(w1));
    int c = n >> 9, d = (n >> 6) & 7, r = n & 63;
    int np = r * 64 + c * 8 + d;                // permuted column
    int slab = np >> 8, nl = np & 255;
    int kh = f2 >> 6, kl = f2 & 63;
    int ch = kl >> 3;                           // 0..7 within k-half row
    uint32_t off = (uint32_t)(nl * 128 + (((ch ^ (nl & 7)) & 7) << 4) + (kl & 7) * 2);
    size_t base = ((size_t)slab * 2 + kh) * 32768 + off;
    *(uint32_t*)(g_Whi + base) = pack2bf(h0, h1);
    *(uint32_t*)(g_Wlo + base) = pack2bf(w0 - h0, w1 - h1);
}

__global__ void prep_x_kernel(const float* __restrict__ X) {
    int idx = blockIdx.x * 256 + threadIdx.x;   // 16384*64
    int row = idx >> 6;
    int k2  = (idx & 63) * 2;
    float2 v = *reinterpret_cast<const float2*>(X + (size_t)row * NF + k2);
    float h0 = __bfloat162float(__float2bfloat16(v.x));
    float h1 = __bfloat162float(__float2bfloat16(v.y));
    int blk = row >> 7, rl = row & 127;
    int ch = k2 >> 3;                           // 0..15
    uint32_t off = (uint32_t)(rl * 256 + ((ch ^ (rl & 7)) << 4) + (k2 & 7) * 2);
    *(uint32_t*)(g_Xhi + (size_t)blk * 32768 + off) = pack2bf(h0, h1);
    *(uint32_t*)(g_Xlo + (size_t)blk * 32768 + off) = pack2bf(v.x - h0, v.y - h1);
}

// ============================================================
// Main kernel: 128 CTAs x 256 threads, warp grid 4(m) x 2(n)
// ============================================================
__global__ __launch_bounds__(256, 1)
void crowds_mma_kernel(const float* __restrict__ p, float* __restrict__ out) {
    extern __shared__ __align__(1024) uint8_t smem[];
    const uint32_t sb = smem_u32(smem);
    float* biasS = (float*)(smem + SM_BIAS);
    float* psS   = (float*)(smem + SM_P);
    float* stage = (float*)(smem + SM_STAGE);

    const int tid = threadIdx.x, lane = tid & 31, warp = tid >> 5;
    const int wm = warp >> 1, wn = warp & 1;    // warp tile 32 x 128
    const int rowbase = blockIdx.x * 128;

    // ---- initial loads: X hi/lo, bias, W image 0; p transpose ----
    {
        const uint8_t* gxh = g_Xhi + (size_t)blockIdx.x * 32768;
        const uint8_t* gxl = g_Xlo + (size_t)blockIdx.x * 32768;
        #pragma unroll
        for (int i = 0; i < 8; i++) {
            int o = (tid + i * 256) * 16;
            cp16(sb + SM_XHI + o, gxh + o);
            cp16(sb + SM_XLO + o, gxl + o);
            cp16(sb + SM_W + o, g_Whi + o);
            cp16(sb + SM_W + 32768 + o, g_Wlo + o);
        }
        #pragma unroll
        for (int i = 0; i < 4; i++) {
            int o = (tid + i * 256) * 16;
            cp16(sb + SM_BIAS + o, (const uint8_t*)g_biasp + o);
        }
        asm volatile("cp.async.commit_group;");
        #pragma unroll
        for (int i = 0; i < 4; i++) {
            int ii = tid + i * 256;
            int row = ii >> 3, c = ii & 7;
            psS[c * 128 + row] = p[(size_t)(rowbase + row) * 8 + c];
        }
    }

    float acc[2][16][4];

    for (int j = 0; j < 32; j++) {
        const int slab = j >> 1, kh = j & 1, slot = j & 1;

        // prefetch next W image
        if (j + 1 < 32) {
            const uint8_t* sh = g_Whi + (size_t)(j + 1) * 32768;
            const uint8_t* sl = g_Wlo + (size_t)(j + 1) * 32768;
            uint32_t dst = sb + SM_W + ((j + 1) & 1) * 65536;
            #pragma unroll
            for (int i = 0; i < 8; i++) {
                int o = (tid + i * 256) * 16;
                cp16(dst + o, sh + o);
                cp16(dst + 32768 + o, sl + o);
            }
            asm volatile("cp.async.commit_group;");
            asm volatile("cp.async.wait_group 1;");
        } else {
            asm volatile("cp.async.wait_group 0;");
        }
        __syncthreads();

        if (kh == 0) {
            #pragma unroll
            for (int mt = 0; mt < 2; mt++)
                #pragma unroll
                for (int nt = 0; nt < 16; nt++)
                    #pragma unroll
                    for (int e = 0; e < 4; e++) acc[mt][nt][e] = 0.f;
        }

        const uint32_t wslot = sb + SM_W + slot * 65536;
        const int arow_base = wm * 32 + (lane & 7) + ((lane >> 3) & 1) * 8;
        const int bn0 = wn * 128 + (lane & 7) + ((lane >> 4) << 3);

        #pragma unroll
        for (int ks = 0; ks < 4; ks++) {
            uint32_t ahi[2][4], alo[2][4];
            const int xch = kh * 8 + ks * 2 + (lane >> 4);
            #pragma unroll
            for (int mt = 0; mt < 2; mt++) {
                int row = arow_base + mt * 16;
                uint32_t aoff = (uint32_t)(row * 256 + ((xch ^ (row & 7)) << 4));
                LDSM4(ahi[mt], sb + SM_XHI + aoff);
                LDSM4(alo[mt], sb + SM_XLO + aoff);
            }
            const int bch = ks * 2 + ((lane >> 3) & 1);
            #pragma unroll
            for (int nb = 0; nb < 2; nb++) {
                uint32_t bh[4][4], bl[4][4];
                #pragma unroll
                for (int t2 = 0; t2 < 4; t2++) {
                    int n = bn0 + nb * 64 + t2 * 16;
                    uint32_t boff = (uint32_t)(n * 128 + (((bch ^ (n & 7)) & 7) << 4));
                    LDSM4(bh[t2], wslot + boff);
                    LDSM4(bl[t2], wslot + 32768 + boff);
                }
                #pragma unroll
                for (int mt = 0; mt < 2; mt++)
                    #pragma unroll
                    for (int t2 = 0; t2 < 4; t2++)
                        #pragma unroll
                        for (int hf = 0; hf < 2; hf++) {
                            float* cacc = acc[mt][nb * 8 + t2 * 2 + hf];
                            mma16816(cacc, ahi[mt], bh[t2][hf * 2], bh[t2][hf * 2 + 1]);
                            mma16816(cacc, ahi[mt], bl[t2][hf * 2], bl[t2][hf * 2 + 1]);
                            mma16816(cacc, alo[mt], bh[t2][hf * 2], bh[t2][hf * 2 + 1]);
                        }
            }
        }

        // ---- epilogue at slab end: softmax over d (quad shuffles) + p ----
        if (kh == 1) {
            const int q = lane & 3, rowq = lane >> 2;
            float of[2][2][4];
            #pragma unroll
            for (int mt = 0; mt < 2; mt++)
                #pragma unroll
                for (int rb = 0; rb < 2; rb++)
                    #pragma unroll
                    for (int e = 0; e < 4; e++) of[mt][rb][e] = 0.f;

            #pragma unroll
            for (int mt = 0; mt < 2; mt++) {
                const int row0 = wm * 32 + mt * 16 + rowq;
                #pragma unroll
                for (int nt = 0; nt < 16; nt++) {
                    const int c = nt & 7, rb = nt >> 3;
                    const int nb_abs = slab * 256 + wn * 128 + nt * 8;
                    float2 bv = *(const float2*)&biasS[nb_abs + q * 2];
                    float e0 = __expf(acc[mt][nt][0] + bv.x);
                    float e1 = __expf(acc[mt][nt][1] + bv.y);
                    float e2 = __expf(acc[mt][nt][2] + bv.x);
                    float e3 = __expf(acc[mt][nt][3] + bv.y);
                    float s0 = e0 + e1, s1 = e2 + e3;
                    s0 += __shfl_xor_sync(0xffffffffu, s0, 1);
                    s0 += __shfl_xor_sync(0xffffffffu, s0, 2);
                    s1 += __shfl_xor_sync(0xffffffffu, s1, 1);
                    s1 += __shfl_xor_sync(0xffffffffu, s1, 2);
                    float f0 = __fdividef(psS[c * 128 + row0], s0);
                    float f1 = __fdividef(psS[c * 128 + row0 + 8], s1);
                    of[mt][rb][0] = fmaf(e0, f0, of[mt][rb][0]);
                    of[mt][rb][1] = fmaf(e1, f0, of[mt][rb][1]);
                    of[mt][rb][2] = fmaf(e2, f1, of[mt][rb][2]);
                    of[mt][rb][3] = fmaf(e3, f1, of[mt][rb][3]);
                }
            }
            __syncthreads();   // all warps done reading slot1 before stage reuse

            #pragma unroll
            for (int mt = 0; mt < 2; mt++) {
                const int row0 = wm * 32 + mt * 16 + rowq;
                #pragma unroll
                for (int rb = 0; rb < 2; rb++) {
                    const int rl = wn * 2 + rb;
                    stage[row0 * 32 + (2 * q) * 4 + rl]           = of[mt][rb][0];
                    stage[row0 * 32 + (2 * q + 1) * 4 + rl]       = of[mt][rb][1];
                    stage[(row0 + 8) * 32 + (2 * q) * 4 + rl]     = of[mt][rb][2];
                    stage[(row0 + 8) * 32 + (2 * q + 1) * 4 + rl] = of[mt][rb][3];
                }
            }
            __syncthreads();

            #pragma unroll
            for (int w = 0; w < 4; w++) {
                int i = tid + w * 256;
                int row = i >> 3, d = i & 7;
                float4 v = *(const float4*)&stage[row * 32 + d * 4];
                *(float4*)&out[(size_t)(rowbase + row) * 512 + d * 64 + slab * 4] = v;
            }
        }
        __syncthreads();       // slot j&1 free for prefetch issued next iter
    }
}

// ============================================================
extern "C" void kernel_launch(void* const* d_in, const int* in_sizes, int n_in,
                              void* d_out, int out_size) {
    const float* x    = (const float*)d_in[0];
    const float* p    = (const float*)d_in[1];
    const float* W    = (const float*)d_in[2];
    const float* bias = (const float*)d_in[3];
    float* out = (float*)d_out;

    int B = in_sizes[0] / NF;                    // 16384

    prep_w_kernel<<<(64 * 4096) / 256, 256>>>(W, bias);
    prep_x_kernel<<<(B * 64) / 256, 256>>>(x);

    cudaFuncSetAttribute(crowds_mma_kernel,
                         cudaFuncAttributeMaxDynamicSharedMemorySize, SM_TOT);
    crowds_mma_kernel<<<B / 128, 256, SM_TOT>>>(p, out);
}